// round 16
// baseline (speedup 1.0000x reference)
#include <cuda_runtime.h>
#include <cuda_bf16.h>
#include <math.h>
#include <stdint.h>

#define SS 1024
#define HH 768
#define KK 32
#define MM 8
#define GG 32
#define VN 32000
#define JT 128

// ---------------- device scratch (static, no runtime alloc) ----------------
__device__ float g_base[SS*HH];
__device__ float g_fpraw[SS*KK*2];
__device__ float g_impraw[SS*KK];
__device__ float g_a1[SS*KK];
__device__ float g_b1[SS*KK];
__device__ float g_lnrm[SS*KK];
__device__ double g_a1d[SS*KK];
__device__ double g_b1d[SS*KK];
__device__ double g_lnd[SS*KK];
__device__ float g_imp[SS*KK];
__device__ float g_Lx[SS];
__device__ float g_L1[SS];
__device__ float g_phi[SS];
__device__ float g_Z[SS*KK];
__device__ float g_P[SS*KK];
__device__ float g_jsp[SS];
__device__ int   g_top[SS*MM];
__device__ float g_sel[SS*MM*HH];
__device__ float g_W2[HH*HH];
__device__ float g_ub[HH];
__device__ float g_kbv[HH];
__device__ float g_kbc_v;
__device__ float g_u[SS*HH];
__device__ float g_ctx[SS*HH];
__device__ float g_ft[SS*HH];
__device__ __nv_bfloat16 g_lmH[(long)VN*HH];
__device__ __nv_bfloat16 g_lmL[(long)VN*HH];
__device__ __nv_bfloat16 g_hidH[SS*HH];
__device__ __nv_bfloat16 g_hidL[SS*HH];

// 32-point Gauss-Legendre on [0,1]
__constant__ float c_node[32] = {
    0.5f*(1.0f-0.0483076656877383162f), 0.5f*(1.0f-0.1444719615827964934f),
    0.5f*(1.0f-0.2392873622521370745f), 0.5f*(1.0f-0.3318686022821276498f),
    0.5f*(1.0f-0.4213512761306353453f), 0.5f*(1.0f-0.5068999089322293900f),
    0.5f*(1.0f-0.5877157572407623290f), 0.5f*(1.0f-0.6630442669302152009f),
    0.5f*(1.0f-0.7321821187402896804f), 0.5f*(1.0f-0.7944837959679424069f),
    0.5f*(1.0f-0.8493676137325699701f), 0.5f*(1.0f-0.8963211557660521240f),
    0.5f*(1.0f-0.9349060759377396892f), 0.5f*(1.0f-0.9647622555875064308f),
    0.5f*(1.0f-0.9856115115452683354f), 0.5f*(1.0f-0.9972638618494815635f),
    0.5f*(1.0f+0.0483076656877383162f), 0.5f*(1.0f+0.1444719615827964934f),
    0.5f*(1.0f+0.2392873622521370745f), 0.5f*(1.0f+0.3318686022821276498f),
    0.5f*(1.0f+0.4213512761306353453f), 0.5f*(1.0f+0.5068999089322293900f),
    0.5f*(1.0f+0.5877157572407623290f), 0.5f*(1.0f+0.6630442669302152009f),
    0.5f*(1.0f+0.7321821187402896804f), 0.5f*(1.0f+0.7944837959679424069f),
    0.5f*(1.0f+0.8493676137325699701f), 0.5f*(1.0f+0.8963211557660521240f),
    0.5f*(1.0f+0.9349060759377396892f), 0.5f*(1.0f+0.9647622555875064308f),
    0.5f*(1.0f+0.9856115115452683354f), 0.5f*(1.0f+0.9972638618494815635f)
};
__constant__ float c_gw[32] = {
    0.5f*0.0965400885147278006f, 0.5f*0.0956387200792748594f,
    0.5f*0.0938443990808045654f, 0.5f*0.0911738786957638847f,
    0.5f*0.0876520930044038111f, 0.5f*0.0833119242269467552f,
    0.5f*0.0781938957870703065f, 0.5f*0.0723457941088485062f,
    0.5f*0.0658222227763618468f, 0.5f*0.0586840934785355471f,
    0.5f*0.0509980592623761762f, 0.5f*0.0428358980222266807f,
    0.5f*0.0342738629130214331f, 0.5f*0.0253920653092620595f,
    0.5f*0.0162743947309056706f, 0.5f*0.0070186100094700966f,
    0.5f*0.0965400885147278006f, 0.5f*0.0956387200792748594f,
    0.5f*0.0938443990808045654f, 0.5f*0.0911738786957638847f,
    0.5f*0.0876520930044038111f, 0.5f*0.0833119242269467552f,
    0.5f*0.0781938957870703065f, 0.5f*0.0723457941088485062f,
    0.5f*0.0658222227763618468f, 0.5f*0.0586840934785355471f,
    0.5f*0.0509980592623761762f, 0.5f*0.0428358980222266807f,
    0.5f*0.0342738629130214331f, 0.5f*0.0253920653092620595f,
    0.5f*0.0162743947309056706f, 0.5f*0.0070186100094700966f
};

__device__ __forceinline__ float softplusf(float x) {
    return fmaxf(x, 0.0f) + log1pf(expf(-fabsf(x)));
}
__device__ __forceinline__ double softplusd(double x) {
    return fmax(x, 0.0) + log1p(exp(-fabs(x)));
}
__device__ __forceinline__ uint32_t smem_u32(const void* p) {
    uint32_t a;
    asm("{ .reg .u64 t; cvta.to.shared.u64 t, %1; cvt.u32.u64 %0, t; }" : "=r"(a) : "l"(p));
    return a;
}
__device__ __forceinline__ void mma16816(float* d, const uint32_t* a, const uint32_t* b) {
    asm volatile(
        "mma.sync.aligned.m16n8k16.row.col.f32.bf16.bf16.f32 "
        "{%0,%1,%2,%3}, {%4,%5,%6,%7}, {%8,%9}, {%0,%1,%2,%3};"
        : "+f"(d[0]), "+f"(d[1]), "+f"(d[2]), "+f"(d[3])
        : "r"(a[0]), "r"(a[1]), "r"(a[2]), "r"(a[3]), "r"(b[0]), "r"(b[1]));
}
__device__ __forceinline__ void ldsm_x4(uint32_t* r, uint32_t addr) {
    asm volatile("ldmatrix.sync.aligned.m8n8.x4.shared.b16 {%0,%1,%2,%3}, [%4];"
        : "=r"(r[0]), "=r"(r[1]), "=r"(r[2]), "=r"(r[3]) : "r"(addr));
}
__device__ __forceinline__ void ldsm_x2(uint32_t* r, uint32_t addr) {
    asm volatile("ldmatrix.sync.aligned.m8n8.x2.shared.b16 {%0,%1}, [%2];"
        : "=r"(r[0]), "=r"(r[1]) : "r"(addr));
}

// -------- split f32 -> bf16 hi/lo pair (grid-stride over float4) -------------
__global__ void cvt_bf16x2_kernel(const float* __restrict__ src,
                                  __nv_bfloat16* __restrict__ dH,
                                  __nv_bfloat16* __restrict__ dL, long n4) {
    long stride = (long)gridDim.x*blockDim.x;
    for (long i = (long)blockIdx.x*blockDim.x + threadIdx.x; i < n4; i += stride) {
        float4 v = ((const float4*)src)[i];
        __nv_bfloat16 h0 = __float2bfloat16(v.x);
        __nv_bfloat16 h1 = __float2bfloat16(v.y);
        __nv_bfloat16 h2 = __float2bfloat16(v.z);
        __nv_bfloat16 h3 = __float2bfloat16(v.w);
        __nv_bfloat16 l0 = __float2bfloat16(v.x - __bfloat162float(h0));
        __nv_bfloat16 l1 = __float2bfloat16(v.y - __bfloat162float(h1));
        __nv_bfloat16 l2 = __float2bfloat16(v.z - __bfloat162float(h2));
        __nv_bfloat16 l3 = __float2bfloat16(v.w - __bfloat162float(h3));
        ((__nv_bfloat162*)dH)[2*i+0] = __nv_bfloat162(h0, h1);
        ((__nv_bfloat162*)dH)[2*i+1] = __nv_bfloat162(h2, h3);
        ((__nv_bfloat162*)dL)[2*i+0] = __nv_bfloat162(l0, l1);
        ((__nv_bfloat162*)dL)[2*i+1] = __nv_bfloat162(l2, l3);
    }
}

// ------------- HMMA bf16x3 GEMM, 512 threads (4 warps/SMSP) ------------------
// CTA tile 128x128, K-chunk 32, 16 warps (4m x 4n), 32x32 per warp.
// Single smem buffer + register prefetch (R13 scheme, doubled warp parallelism).
#define GMM 128
#define GNN 128
#define GKC 32
#define SRD 40

__global__ __launch_bounds__(512, 1) void gemm_bf3(
    const __nv_bfloat16* __restrict__ AH, const __nv_bfloat16* __restrict__ AL,
    const __nv_bfloat16* __restrict__ BH, const __nv_bfloat16* __restrict__ BL,
    float* __restrict__ C, int Mr, int Nr, int Kr)
{
    __shared__ __align__(16) __nv_bfloat16 sAh[GMM*SRD];
    __shared__ __align__(16) __nv_bfloat16 sAl[GMM*SRD];
    __shared__ __align__(16) __nv_bfloat16 sBh[GNN*SRD];
    __shared__ __align__(16) __nv_bfloat16 sBl[GNN*SRD];

    int tid = threadIdx.x;
    int wid = tid >> 5, lane = tid & 31;
    int wm = wid & 3, wn = wid >> 2;      // 4x4 warp grid, 32x32 tile each
    long row0 = (long)blockIdx.y * GMM;
    long col0 = (long)blockIdx.x * GNN;

    float d[2][4][4];
    #pragma unroll
    for (int i = 0; i < 2; i++)
        #pragma unroll
        for (int j = 0; j < 4; j++)
            #pragma unroll
            for (int r = 0; r < 4; r++) d[i][j][r] = 0.f;

    uint32_t aAh = smem_u32(sAh), aAl = smem_u32(sAl);
    uint32_t aBh = smem_u32(sBh), aBl = smem_u32(sBl);

    int lrowA = lane & 15;
    int lcolA = ((lane >> 4) & 1) * 8;
    int lrowB = lane & 7;
    int lcolB = ((lane >> 3) & 1) * 8;

    // load slots: 1024 uint2 per array / 512 threads = 2 each
    int lr[2], lq[2];
    #pragma unroll
    for (int l = 0; l < 2; l++) {
        int idx = tid + l*512;
        lr[l] = idx >> 3;
        lq[l] = idx & 7;
    }

    uint2 rAh[2], rAl[2], rBh[2], rBl[2];
    #pragma unroll
    for (int l = 0; l < 2; l++) {
        long goff = (row0 + lr[l])*Kr + lq[l]*4;
        long boff = (col0 + lr[l])*Kr + lq[l]*4;
        rAh[l] = *(const uint2*)(AH + goff);
        rAl[l] = *(const uint2*)(AL + goff);
        rBh[l] = *(const uint2*)(BH + boff);
        rBl[l] = *(const uint2*)(BL + boff);
    }
    #pragma unroll
    for (int l = 0; l < 2; l++) {
        int e = lr[l]*SRD + lq[l]*4;
        *(uint2*)&sAh[e] = rAh[l];
        *(uint2*)&sAl[e] = rAl[l];
        *(uint2*)&sBh[e] = rBh[l];
        *(uint2*)&sBl[e] = rBl[l];
    }
    __syncthreads();

    int nch = Kr / GKC;
    for (int c = 0; c < nch; c++) {
        bool has_next = (c + 1 < nch);
        if (has_next) {
            int kb = (c+1)*GKC;
            #pragma unroll
            for (int l = 0; l < 2; l++) {
                long goff = (row0 + lr[l])*Kr + kb + lq[l]*4;
                long boff = (col0 + lr[l])*Kr + kb + lq[l]*4;
                rAh[l] = *(const uint2*)(AH + goff);
                rAl[l] = *(const uint2*)(AL + goff);
                rBh[l] = *(const uint2*)(BH + boff);
                rBl[l] = *(const uint2*)(BL + boff);
            }
        }

        #pragma unroll
        for (int ks = 0; ks < 2; ks++) {
            uint32_t ah[2][4], al[2][4], bh[4][2], bl[4][2];
            #pragma unroll
            for (int mt = 0; mt < 2; mt++) {
                int row = wm*32 + mt*16 + lrowA;
                uint32_t off = (uint32_t)(row*SRD + ks*16 + lcolA) * 2u;
                ldsm_x4(ah[mt], aAh + off);
                ldsm_x4(al[mt], aAl + off);
            }
            #pragma unroll
            for (int nt = 0; nt < 4; nt++) {
                int row = wn*32 + nt*8 + lrowB;
                uint32_t off = (uint32_t)(row*SRD + ks*16 + lcolB) * 2u;
                ldsm_x2(bh[nt], aBh + off);
                ldsm_x2(bl[nt], aBl + off);
            }
            #pragma unroll
            for (int mt = 0; mt < 2; mt++)
                #pragma unroll
                for (int nt = 0; nt < 4; nt++) {
                    mma16816(d[mt][nt], ah[mt], bh[nt]);
                    mma16816(d[mt][nt], ah[mt], bl[nt]);
                    mma16816(d[mt][nt], al[mt], bh[nt]);
                }
        }
        __syncthreads();
        if (has_next) {
            #pragma unroll
            for (int l = 0; l < 2; l++) {
                int e = lr[l]*SRD + lq[l]*4;
                *(uint2*)&sAh[e] = rAh[l];
                *(uint2*)&sAl[e] = rAl[l];
                *(uint2*)&sBh[e] = rBh[l];
                *(uint2*)&sBl[e] = rBl[l];
            }
            __syncthreads();
        }
    }

    #pragma unroll
    for (int mt = 0; mt < 2; mt++) {
        long r0 = row0 + wm*32 + mt*16 + (lane >> 2);
        #pragma unroll
        for (int nt = 0; nt < 4; nt++) {
            long cc = col0 + wn*32 + nt*8 + (lane & 3)*2;
            *(float2*)(C + r0*Nr + cc)     = make_float2(d[mt][nt][0], d[mt][nt][1]);
            *(float2*)(C + (r0+8)*Nr + cc) = make_float2(d[mt][nt][2], d[mt][nt][3]);
        }
    }
}

// -------- merged: gather base row + logs + phi dot (one block per j) ---------
__global__ __launch_bounds__(768) void prep_kernel(const int* __restrict__ ids,
                                                   const float* __restrict__ emb,
                                                   const float* __restrict__ gw) {
    int j = blockIdx.x;
    int tid = threadIdx.x;
    __shared__ float red[24];
    int id = ids[j];
    float v = emb[(long)id*HH + tid];
    g_base[j*HH + tid] = v;
    float s = v * gw[HH + tid];
    #pragma unroll
    for (int o = 16; o; o >>= 1) s += __shfl_xor_sync(0xffffffffu, s, o);
    int w = tid >> 5, lane = tid & 31;
    if (lane == 0) red[w] = s;
    __syncthreads();
    if (tid == 0) {
        float tot = 0.f;
        for (int i = 0; i < 24; i++) tot += red[i];
        g_phi[j] = tot;
        float x = ((float)j + 0.5f) * (1.0f/(float)SS);
        x = fminf(fmaxf(x, 1e-5f), 1.0f - 1e-5f);
        g_Lx[j] = logf(x);
        g_L1[j] = log1pf(-x);
    }
}

// focus (64) + imp (32) projections, one block per t
__global__ __launch_bounds__(256) void proj96_kernel(
    const float* __restrict__ hpen,
    const float* __restrict__ fw, const float* __restrict__ fb,
    const float* __restrict__ iw, const float* __restrict__ ib)
{
    int t = blockIdx.x, tid = threadIdx.x;
    int w = tid >> 5, lane = tid & 31;
    __shared__ float row[HH];
    for (int h = tid; h < HH; h += 256) row[h] = hpen[t*HH + h];
    __syncthreads();
    #pragma unroll
    for (int i = 0; i < 12; i++) {
        int n = w*12 + i;
        const float* W = (n < 64) ? (fw + (long)n*HH) : (iw + (long)(n-64)*HH);
        float s = 0.f;
        for (int h = lane; h < HH; h += 32) s += row[h]*W[h];
        #pragma unroll
        for (int o = 16; o; o >>= 1) s += __shfl_xor_sync(0xffffffffu, s, o);
        if (lane == 0) {
            if (n < 64) g_fpraw[t*64 + n] = s + fb[n];
            else        g_impraw[t*32 + n - 64] = s + ib[n-64];
        }
    }
}

// ------------- merged params (softplus+lgamma) + warp top-k ------------------
__global__ void params_topk_kernel() {
    int t = blockIdx.x, k = threadIdx.x;   // 32 threads
    float fa = 0.f, fb = 0.f, im = 0.f;
    if (t > 0) {
        fa = g_fpraw[(t-1)*(KK*2) + k*2 + 0];
        fb = g_fpraw[(t-1)*(KK*2) + k*2 + 1];
        im = softplusf(g_impraw[(t-1)*KK + k]);
    }
    double al = softplusd((double)fa) + 1e-4;
    double be = softplusd((double)fb) + 1e-4;
    double ln = lgamma(al) + lgamma(be) - lgamma(al + be);
    g_a1d[t*KK+k] = al - 1.0;
    g_b1d[t*KK+k] = be - 1.0;
    g_lnd[t*KK+k] = ln;
    g_a1[t*KK+k] = (float)(al - 1.0);
    g_b1[t*KK+k] = (float)(be - 1.0);
    g_lnrm[t*KK+k] = (float)ln;
    g_imp[t*KK+k] = im;
    float v = im;
    for (int m = 0; m < MM; m++) {
        float bv = v; int bi = k;
        #pragma unroll
        for (int o = 16; o; o >>= 1) {
            float ov = __shfl_xor_sync(0xffffffffu, bv, o);
            int oi = __shfl_xor_sync(0xffffffffu, bi, o);
            if (ov > bv || (ov == bv && oi < bi)) { bv = ov; bi = oi; }
        }
        if (k == 0) g_top[t*MM + m] = bi;
        if (k == bi) v = -__int_as_float(0x7f800000);
    }
}

// ---- Z[t,k] = sum_j pdf, P[t,k] = sum_j pdf*phi[j]  (longest-first order) ---
__global__ __launch_bounds__(256) void zsum_kernel() {
    int t = SS - 1 - blockIdx.x;
    int tid = threadIdx.x;
    int k = tid & 31, jg = tid >> 5;
    __shared__ float a1s[KK], b1s[KK], lns[KK];
    __shared__ float rz[256], rp[256];
    if (tid < KK) {
        a1s[tid] = g_a1[t*KK+tid];
        b1s[tid] = g_b1[t*KK+tid];
        lns[tid] = g_lnrm[t*KK+tid];
    }
    __syncthreads();
    float a = a1s[k], b = b1s[k], ln = lns[k];
    float z = 0.f, p = 0.f;
    for (int j = jg; j <= t; j += 8) {
        float e = __expf(fmaf(a, g_Lx[j], fmaf(b, g_L1[j], -ln)));
        z += e;
        p = fmaf(e, g_phi[j], p);
    }
    rz[tid] = z; rp[tid] = p;
    __syncthreads();
    if (tid < KK) {
        float sz = 0.f, sp = 0.f;
        #pragma unroll
        for (int g = 0; g < 8; g++) { sz += rz[g*32 + tid]; sp += rp[g*32 + tid]; }
        g_Z[t*KK + tid] = sz;
        g_P[t*KK + tid] = sp;
    }
}

// ---- chunk rows for top-8 k, TWO t per block (longest-first pairs) ----------
__global__ __launch_bounds__(768, 2) void chunksel_kernel() {
    int pidx = (SS/2) - 1 - blockIdx.x;     // pair index, longest first
    int t0 = 2*pidx;
    int t1 = t0 + 1;
    int tid = threadIdx.x;
    __shared__ float a16[16], b16[16], l16[16], sca16[16];
    __shared__ float buf[2][JT*16];

    if (tid < 16) {
        int tt = t0 + (tid >> 3);
        int k = g_top[tt*MM + (tid & 7)];
        a16[tid] = g_a1[tt*KK + k];
        b16[tid] = g_b1[tt*KK + k];
        l16[tid] = g_lnrm[tt*KK + k];
        sca16[tid] = g_imp[tt*KK + k] / (g_Z[tt*KK + k] + 1e-9f);
    }
    __syncthreads();

    float acc[16];
    #pragma unroll
    for (int m = 0; m < 16; m++) acc[m] = 0.f;

    int ntiles = (t1 + JT) / JT;

    for (int v = tid; v < JT*16; v += 768) {
        int jl = v >> 4, s = v & 15;
        int tt = t0 + (s >> 3);
        float e = 0.f;
        if (jl <= tt)
            e = __expf(fmaf(a16[s], g_Lx[jl], fmaf(b16[s], g_L1[jl], -l16[s])));
        buf[0][v] = e;
    }
    __syncthreads();

    for (int tile = 0; tile < ntiles; tile++) {
        int p = tile & 1;
        if (tile + 1 < ntiles) {
            int jb = (tile+1)*JT;
            for (int v = tid; v < JT*16; v += 768) {
                int jl = v >> 4, s = v & 15;
                int j = jb + jl;
                int tt = t0 + (s >> 3);
                float e = 0.f;
                if (j <= tt)
                    e = __expf(fmaf(a16[s], g_Lx[j], fmaf(b16[s], g_L1[j], -l16[s])));
                buf[1-p][v] = e;
            }
        }
        int jb = tile*JT;
        int jend = min(jb + JT - 1, t1);
        #pragma unroll 2
        for (int j = jb; j <= jend; j++) {
            float b = g_base[j*HH + tid];
            const float4* w4 = (const float4*)&buf[p][(j - jb)*16];
            #pragma unroll
            for (int q = 0; q < 4; q++) {
                float4 w = w4[q];
                acc[4*q+0] = fmaf(w.x, b, acc[4*q+0]);
                acc[4*q+1] = fmaf(w.y, b, acc[4*q+1]);
                acc[4*q+2] = fmaf(w.z, b, acc[4*q+2]);
                acc[4*q+3] = fmaf(w.w, b, acc[4*q+3]);
            }
        }
        __syncthreads();
    }

    #pragma unroll
    for (int m = 0; m < MM; m++) {
        g_sel[((long)t0*MM + m)*HH + tid] = acc[m]     * sca16[m];
        g_sel[((long)t1*MM + m)*HH + tid] = acc[8 + m] * sca16[8 + m];
    }
}

// ------------------------ generic SGEMM: C = A @ B^T + bias ----------------
#define BM 64
#define BN 64
#define BK 16
__global__ __launch_bounds__(256) void sgemm_bias(
    const float* __restrict__ A, const float* __restrict__ B,
    const float* __restrict__ bias, float* __restrict__ C,
    int Mr, int Nr, int Kr)
{
    __shared__ float As[BK][BM+4];
    __shared__ float Bs[BK][BN+4];
    int tx = threadIdx.x & 15;
    int ty = threadIdx.x >> 4;
    int row0 = blockIdx.y*BM;
    int col0 = blockIdx.x*BN;
    float acc[4][4];
    #pragma unroll
    for (int i = 0; i < 4; i++)
        #pragma unroll
        for (int j = 0; j < 4; j++) acc[i][j] = 0.f;

    for (int k0 = 0; k0 < Kr; k0 += BK) {
        #pragma unroll
        for (int l = 0; l < 4; l++) {
            int lin = threadIdx.x + l*256;
            int r = lin >> 4, c = lin & 15;
            int gr = row0 + r;
            As[c][r] = (gr < Mr) ? A[(long)gr*Kr + k0 + c] : 0.f;
        }
        #pragma unroll
        for (int l = 0; l < 4; l++) {
            int lin = threadIdx.x + l*256;
            int r = lin >> 4, c = lin & 15;
            int gc = col0 + r;
            Bs[c][r] = (gc < Nr) ? B[(long)gc*Kr + k0 + c] : 0.f;
        }
        __syncthreads();
        #pragma unroll
        for (int c = 0; c < BK; c++) {
            float4 a4 = *(const float4*)&As[c][ty*4];
            float4 b4 = *(const float4*)&Bs[c][tx*4];
            float ar[4] = {a4.x, a4.y, a4.z, a4.w};
            float br[4] = {b4.x, b4.y, b4.z, b4.w};
            #pragma unroll
            for (int i = 0; i < 4; i++)
                #pragma unroll
                for (int j = 0; j < 4; j++)
                    acc[i][j] = fmaf(ar[i], br[j], acc[i][j]);
        }
        __syncthreads();
    }
    #pragma unroll
    for (int i = 0; i < 4; i++) {
        int gr = row0 + ty*4 + i;
        if (gr >= Mr) continue;
        #pragma unroll
        for (int j = 0; j < 4; j++) {
            int gc = col0 + tx*4 + j;
            if (gc >= Nr) continue;
            float v = acc[i][j];
            if (bias) v += bias[gc];
            C[(long)gr*Nr + gc] = v;
        }
    }
}

// ---------- SGEMM-TN: C[i,j] = sum_k A[k,i] * B[k,j] -------------------------
__global__ __launch_bounds__(256) void sgemm_tn(
    const float* __restrict__ A, const float* __restrict__ B,
    float* __restrict__ C, int Mr, int Nr, int Kr)
{
    __shared__ float As[BK][BM+4];
    __shared__ float Bs[BK][BN+4];
    int tx = threadIdx.x & 15;
    int ty = threadIdx.x >> 4;
    int row0 = blockIdx.y*BM;
    int col0 = blockIdx.x*BN;
    float acc[4][4];
    #pragma unroll
    for (int i = 0; i < 4; i++)
        #pragma unroll
        for (int j = 0; j < 4; j++) acc[i][j] = 0.f;

    for (int k0 = 0; k0 < Kr; k0 += BK) {
        #pragma unroll
        for (int l = 0; l < 4; l++) {
            int lin = threadIdx.x + l*256;
            int r = lin & 63, c = lin >> 6;
            As[c][r] = A[(long)(k0 + c)*Mr + row0 + r];
        }
        #pragma unroll
        for (int l = 0; l < 4; l++) {
            int lin = threadIdx.x + l*256;
            int r = lin & 63, c = lin >> 6;
            Bs[c][r] = B[(long)(k0 + c)*Nr + col0 + r];
        }
        __syncthreads();
        #pragma unroll
        for (int c = 0; c < BK; c++) {
            float4 a4 = *(const float4*)&As[c][ty*4];
            float4 b4 = *(const float4*)&Bs[c][tx*4];
            float ar[4] = {a4.x, a4.y, a4.z, a4.w};
            float br[4] = {b4.x, b4.y, b4.z, b4.w};
            #pragma unroll
            for (int i = 0; i < 4; i++)
                #pragma unroll
                for (int j = 0; j < 4; j++)
                    acc[i][j] = fmaf(ar[i], br[j], acc[i][j]);
        }
        __syncthreads();
    }
    #pragma unroll
    for (int i = 0; i < 4; i++) {
        int gr = row0 + ty*4 + i;
        #pragma unroll
        for (int j = 0; j < 4; j++)
            C[(long)gr*Nr + col0 + tx*4 + j] = acc[i][j];
    }
}

// ---- ub[h'] = qb.kw[:,h'];  kbv[hf] = qw[:,hf].kb;  kbc = qb.kb -------------
__global__ void prebias_kernel(const float* __restrict__ qw, const float* __restrict__ qb,
                               const float* __restrict__ kw, const float* __restrict__ kb) {
    int i = blockIdx.x*256 + threadIdx.x;
    if (i < HH) {
        float s = 0.f;
        for (int h = 0; h < HH; h++) s = fmaf(qb[h], kw[(long)h*HH + i], s);
        g_ub[i] = s;
    } else if (i < 2*HH) {
        int j = i - HH;
        float s = 0.f;
        for (int h = 0; h < HH; h++) s = fmaf(qw[(long)h*HH + j], kb[h], s);
        g_kbv[j] = s;
    } else if (i == 2*HH) {
        float s = 0.f;
        for (int h = 0; h < HH; h++) s = fmaf(qb[h], kb[h], s);
        g_kbc_v = s;
    }
}

// ------------------------------- attention -----------------------------------
__global__ __launch_bounds__(288) void attn2_kernel(const float* __restrict__ hfin) {
    int t = blockIdx.x, tid = threadIdx.x;
    int w = tid >> 5, lane = tid & 31;
    __shared__ float sc[9], at[MM];
    float s = 0.f;
    if (w < MM) {
        const float* sel = g_sel + ((long)t*MM + w)*HH;
        for (int h = lane; h < HH; h += 32) s += g_u[t*HH + h]*sel[h];
    } else {
        for (int h = lane; h < HH; h += 32) s += hfin[t*HH + h]*g_kbv[h];
    }
    #pragma unroll
    for (int o = 16; o; o >>= 1) s += __shfl_xor_sync(0xffffffffu, s, o);
    if (lane == 0) sc[w] = s;
    __syncthreads();
    if (tid == 0) {
        float extra = sc[8] + g_kbc_v;
        const float isq = 1.0f/27.712812921102035f;
        float v[MM], mx = -3.4e38f;
        for (int m = 0; m < MM; m++) { v[m] = (sc[m] + extra)*isq; mx = fmaxf(mx, v[m]); }
        float ssum = 0.f;
        for (int m = 0; m < MM; m++) { float e = expf(v[m]-mx); at[m] = e; ssum += e; }
        float inv = 1.0f/ssum;
        for (int m = 0; m < MM; m++) at[m] *= inv;
    }
    __syncthreads();
    for (int h = tid; h < HH; h += 288) {
        float f = 0.f;
        #pragma unroll
        for (int m = 0; m < MM; m++)
            f = fmaf(at[m], g_sel[((long)t*MM + m)*HH + h], f);
        g_ctx[t*HH + h] = f;
    }
}

// ---------------------- merged gate + gated residual + LN -------------------
__global__ __launch_bounds__(256) void lngate_kernel(const float* __restrict__ hpen,
                                                     const float* __restrict__ gw,
                                                     const float* __restrict__ gb,
                                                     const float* __restrict__ hfin,
                                                     const float* __restrict__ lng,
                                                     const float* __restrict__ lnb) {
    int t = blockIdx.x, tid = threadIdx.x;
    __shared__ float hb[HH];
    __shared__ float red[8];
    __shared__ float s_gate, s_mean, s_var;
    int w = tid >> 5, lane = tid & 31;

    float s = 0.f;
    for (int h = tid; h < HH; h += 256)
        s += hpen[t*HH+h]*gw[h];
    #pragma unroll
    for (int o = 16; o; o >>= 1) s += __shfl_xor_sync(0xffffffffu, s, o);
    if (lane == 0) red[w] = s;
    __syncthreads();
    if (tid == 0) {
        float tot = 0.f;
        for (int i = 0; i < 8; i++) tot += red[i];
        float s2 = 0.f;
        for (int k = 0; k < KK; k++)
            s2 = fmaf(g_imp[t*KK+k]/(g_Z[t*KK+k]+1e-9f), g_P[t*KK+k], s2);
        s2 *= (1.0f/(float)KK);
        s_gate = 1.0f/(1.0f + expf(-(tot + s2 + gb[0])));
    }
    __syncthreads();

    float gt = s_gate;
    s = 0.f;
    for (int h = tid; h < HH; h += 256) {
        float hv = gt*g_ft[t*HH+h] + (1.0f-gt)*hfin[t*HH+h];
        hb[h] = hv;
        s += hv;
    }
    #pragma unroll
    for (int o = 16; o; o >>= 1) s += __shfl_xor_sync(0xffffffffu, s, o);
    if (lane == 0) red[w] = s;
    __syncthreads();
    if (tid == 0) {
        float tot = 0.f;
        for (int i = 0; i < 8; i++) tot += red[i];
        s_mean = tot * (1.0f/(float)HH);
    }
    __syncthreads();
    float mean = s_mean;
    float v = 0.f;
    for (int h = tid; h < HH; h += 256) {
        float dd = hb[h] - mean;
        v += dd*dd;
    }
    #pragma unroll
    for (int o = 16; o; o >>= 1) v += __shfl_xor_sync(0xffffffffu, v, o);
    if (lane == 0) red[w] = v;
    __syncthreads();
    if (tid == 0) {
        float tot = 0.f;
        for (int i = 0; i < 8; i++) tot += red[i];
        s_var = tot * (1.0f/(float)HH);
    }
    __syncthreads();
    float inv = rsqrtf(s_var + 1e-5f);
    for (int h = tid; h < HH; h += 256) {
        float hv = (hb[h]-mean)*inv*lng[h] + lnb[h];
        __nv_bfloat16 hh = __float2bfloat16(hv);
        g_hidH[t*HH+h] = hh;
        g_hidL[t*HH+h] = __float2bfloat16(hv - __bfloat162float(hh));
    }
}

// ------------------------------- JS divergence -------------------------------
__global__ __launch_bounds__(512) void js_kernel() {
    int t = blockIdx.x;
    int tid = threadIdx.x;
    __shared__ double pd[KK*GG];
    __shared__ double a1s[KK], b1s[KK], lns[KK];
    __shared__ double lgx[GG], lg1[GG];
    __shared__ float gws[GG];
    __shared__ float red[16];

    if (tid < KK) {
        a1s[tid] = g_a1d[t*KK+tid];
        b1s[tid] = g_b1d[t*KK+tid];
        lns[tid] = g_lnd[t*KK+tid];
        double nd = (double)c_node[tid];
        nd = fmin(fmax(nd, 1e-5), 1.0 - 1e-5);
        lgx[tid] = log(nd);
        lg1[tid] = log1p(-nd);
        gws[tid] = c_gw[tid];
    }
    __syncthreads();
    for (int v = tid; v < KK*GG; v += 512) {
        int k = v >> 5, g = v & 31;
        pd[v] = exp(a1s[k]*lgx[g] + b1s[k]*lg1[g] - lns[k]);
    }
    __syncthreads();

    float sum = 0.f;
    if (tid < 496) {
        int idx = tid, i = 0, rem = 31;
        while (idx >= rem) { idx -= rem; i++; rem--; }
        int j = i + 1 + idx;
        #pragma unroll
        for (int g = 0; g < GG; g++) {
            double pi = pd[i*GG+g], pj = pd[j*GG+g];
            double me = 0.5*(pi+pj) + 1e-9;
            double dd = 0.5*(pi-pj);
            float inv = 1.0f/(float)me;
            float rr = (float)dd * inv;
            float term = (float)pi * log1pf(rr) + (float)pj * log1pf(-rr);
            sum += gws[g]*0.5f*term;
        }
    }
    #pragma unroll
    for (int o = 16; o; o >>= 1) sum += __shfl_xor_sync(0xffffffffu, sum, o);
    int w = tid >> 5, lane = tid & 31;
    if (lane == 0) red[w] = sum;
    __syncthreads();
    if (tid == 0) {
        float s = 0.f;
        for (int i = 0; i < 16; i++) s += red[i];
        g_jsp[t] = s;
    }
}

__global__ void jsred_kernel(float* out, int out_size) {
    __shared__ double smr[SS];
    int tid = threadIdx.x;
    smr[tid] = (double)g_jsp[tid];
    __syncthreads();
    for (int s = SS/2; s; s >>= 1) {
        if (tid < s) smr[tid] += smr[tid+s];
        __syncthreads();
    }
    if (tid == 0) out[out_size-1] = (float)(smr[0] / 507904.0);
}

// ------------------------------------------------------------------------------
extern "C" void kernel_launch(void* const* d_in, const int* in_sizes, int n_in,
                              void* d_out, int out_size) {
    const int*   ids     = (const int*)  d_in[0];
    const float* emb     = (const float*)d_in[1];
    const float* h_pen   = (const float*)d_in[2];
    const float* h_final = (const float*)d_in[3];
    const float* focus_w = (const float*)d_in[4];
    const float* focus_b = (const float*)d_in[5];
    const float* imp_w   = (const float*)d_in[6];
    const float* imp_b   = (const float*)d_in[7];
    const float* q_w     = (const float*)d_in[8];
    const float* q_b     = (const float*)d_in[9];
    const float* k_w     = (const float*)d_in[10];
    const float* k_b     = (const float*)d_in[11];
    const float* v_w     = (const float*)d_in[12];
    const float* v_b     = (const float*)d_in[13];
    const float* gate_w  = (const float*)d_in[14];
    const float* gate_b  = (const float*)d_in[15];
    const float* ln_g    = (const float*)d_in[16];
    const float* ln_b    = (const float*)d_in[17];
    const float* lm_w    = (const float*)d_in[18];
    float* out = (float*)d_out;

    float* p_W2;  cudaGetSymbolAddress((void**)&p_W2,  g_W2);
    float* p_ub;  cudaGetSymbolAddress((void**)&p_ub,  g_ub);
    float* p_u;   cudaGetSymbolAddress((void**)&p_u,   g_u);
    float* p_ctx; cudaGetSymbolAddress((void**)&p_ctx, g_ctx);
    float* p_ft;  cudaGetSymbolAddress((void**)&p_ft,  g_ft);
    __nv_bfloat16 *p_lmH, *p_lmL, *p_hidH, *p_hidL;
    cudaGetSymbolAddress((void**)&p_lmH,  g_lmH);
    cudaGetSymbolAddress((void**)&p_lmL,  g_lmL);
    cudaGetSymbolAddress((void**)&p_hidH, g_hidH);
    cudaGetSymbolAddress((void**)&p_hidL, g_hidL);

    static cudaStream_t s1 = nullptr, s2 = nullptr;
    static cudaEvent_t evA = nullptr, evB = nullptr, ev1 = nullptr, ev2 = nullptr, evL = nullptr;
    if (!s1) {
        cudaStreamCreateWithFlags(&s1, cudaStreamNonBlocking);
        cudaStreamCreateWithFlags(&s2, cudaStreamNonBlocking);
        cudaEventCreateWithFlags(&evA, cudaEventDisableTiming);
        cudaEventCreateWithFlags(&evB, cudaEventDisableTiming);
        cudaEventCreateWithFlags(&ev1, cudaEventDisableTiming);
        cudaEventCreateWithFlags(&ev2, cudaEventDisableTiming);
        cudaEventCreateWithFlags(&evL, cudaEventDisableTiming);
    }

    // ---- fork branch A: attention pre-work + lm_w bf16 split ----
    cudaEventRecord(evA, 0);
    cudaStreamWaitEvent(s1, evA, 0);
    sgemm_tn<<<dim3(HH/BN, HH/BM), 256, 0, s1>>>(k_w, q_w, p_W2, HH, HH, HH);
    prebias_kernel<<<7, 256, 0, s1>>>(q_w, q_b, k_w, k_b);
    sgemm_bias<<<dim3(HH/BN, SS/BM), 256, 0, s1>>>(h_final, p_W2, p_ub, p_u, SS, HH, HH);
    cudaEventRecord(ev1, s1);
    cvt_bf16x2_kernel<<<4096, 256, 0, s1>>>(lm_w, p_lmH, p_lmL, (long)VN*HH/4);
    cudaEventRecord(evL, s1);

    // ---- main chain ----
    prep_kernel<<<SS, HH>>>(ids, emb, gate_w);
    proj96_kernel<<<SS, 256>>>(h_pen, focus_w, focus_b, imp_w, imp_b);
    params_topk_kernel<<<SS, KK>>>();

    // ---- fork branch B: JS loss ----
    cudaEventRecord(evB, 0);
    cudaStreamWaitEvent(s2, evB, 0);
    js_kernel<<<SS, 512, 0, s2>>>();
    jsred_kernel<<<1, SS, 0, s2>>>(out, out_size);
    cudaEventRecord(ev2, s2);

    zsum_kernel<<<SS, 256>>>();
    chunksel_kernel<<<SS/2, HH>>>();

    cudaStreamWaitEvent(0, ev1, 0);
    attn2_kernel<<<SS, 288>>>(h_final);
    sgemm_bias<<<dim3(HH/BN, SS/BM), 256>>>(p_ctx, v_w, v_b, p_ft, SS, HH, HH);
    lngate_kernel<<<SS, 256>>>(h_pen, gate_w, gate_b, h_final, ln_g, ln_b);

    // ---- LM head on tensor pipe (bf16x3, 512-thread, 4 warps/SMSP) ----
    cudaStreamWaitEvent(0, evL, 0);
    gemm_bf3<<<dim3(VN/GNN, SS/GMM), 512>>>(p_hidH, p_hidL, p_lmH, p_lmL, out, SS, VN, HH);

    // ---- join branch B ----
    cudaStreamWaitEvent(0, ev2, 0);
}

// round 17
// speedup vs baseline: 1.0883x; 1.0883x over previous
#include <cuda_runtime.h>
#include <cuda_bf16.h>
#include <math.h>
#include <stdint.h>

#define SS 1024
#define HH 768
#define KK 32
#define MM 8
#define GG 32
#define VN 32000
#define JT 128
#define HS (SS/2)

// ---------------- device scratch (static, no runtime alloc) ----------------
__device__ float g_base[SS*HH];
__device__ float g_fpraw[SS*KK*2];
__device__ float g_impraw[SS*KK];
__device__ float g_a1[SS*KK];
__device__ float g_b1[SS*KK];
__device__ float g_lnrm[SS*KK];
__device__ double g_a1d[SS*KK];
__device__ double g_b1d[SS*KK];
__device__ double g_lnd[SS*KK];
__device__ float g_imp[SS*KK];
__device__ float g_Lx[SS];
__device__ float g_L1[SS];
__device__ float g_phi[SS];
__device__ float g_Z[SS*KK];
__device__ float g_P[SS*KK];
__device__ float g_jsp[SS];
__device__ int   g_top[SS*MM];
__device__ float g_sel[SS*MM*HH];
__device__ float g_W2[HH*HH];
__device__ float g_ub[HH];
__device__ float g_kbv[HH];
__device__ float g_kbc_v;
__device__ float g_u[SS*HH];
__device__ float g_ctx[SS*HH];
__device__ float g_ft[SS*HH];
__device__ __nv_bfloat16 g_lmH[(long)VN*HH];
__device__ __nv_bfloat16 g_lmL[(long)VN*HH];
__device__ __nv_bfloat16 g_hidH[SS*HH];
__device__ __nv_bfloat16 g_hidL[SS*HH];

// 32-point Gauss-Legendre on [0,1]
__constant__ float c_node[32] = {
    0.5f*(1.0f-0.0483076656877383162f), 0.5f*(1.0f-0.1444719615827964934f),
    0.5f*(1.0f-0.2392873622521370745f), 0.5f*(1.0f-0.3318686022821276498f),
    0.5f*(1.0f-0.4213512761306353453f), 0.5f*(1.0f-0.5068999089322293900f),
    0.5f*(1.0f-0.5877157572407623290f), 0.5f*(1.0f-0.6630442669302152009f),
    0.5f*(1.0f-0.7321821187402896804f), 0.5f*(1.0f-0.7944837959679424069f),
    0.5f*(1.0f-0.8493676137325699701f), 0.5f*(1.0f-0.8963211557660521240f),
    0.5f*(1.0f-0.9349060759377396892f), 0.5f*(1.0f-0.9647622555875064308f),
    0.5f*(1.0f-0.9856115115452683354f), 0.5f*(1.0f-0.9972638618494815635f),
    0.5f*(1.0f+0.0483076656877383162f), 0.5f*(1.0f+0.1444719615827964934f),
    0.5f*(1.0f+0.2392873622521370745f), 0.5f*(1.0f+0.3318686022821276498f),
    0.5f*(1.0f+0.4213512761306353453f), 0.5f*(1.0f+0.5068999089322293900f),
    0.5f*(1.0f+0.5877157572407623290f), 0.5f*(1.0f+0.6630442669302152009f),
    0.5f*(1.0f+0.7321821187402896804f), 0.5f*(1.0f+0.7944837959679424069f),
    0.5f*(1.0f+0.8493676137325699701f), 0.5f*(1.0f+0.8963211557660521240f),
    0.5f*(1.0f+0.9349060759377396892f), 0.5f*(1.0f+0.9647622555875064308f),
    0.5f*(1.0f+0.9856115115452683354f), 0.5f*(1.0f+0.9972638618494815635f)
};
__constant__ float c_gw[32] = {
    0.5f*0.0965400885147278006f, 0.5f*0.0956387200792748594f,
    0.5f*0.0938443990808045654f, 0.5f*0.0911738786957638847f,
    0.5f*0.0876520930044038111f, 0.5f*0.0833119242269467552f,
    0.5f*0.0781938957870703065f, 0.5f*0.0723457941088485062f,
    0.5f*0.0658222227763618468f, 0.5f*0.0586840934785355471f,
    0.5f*0.0509980592623761762f, 0.5f*0.0428358980222266807f,
    0.5f*0.0342738629130214331f, 0.5f*0.0253920653092620595f,
    0.5f*0.0162743947309056706f, 0.5f*0.0070186100094700966f,
    0.5f*0.0965400885147278006f, 0.5f*0.0956387200792748594f,
    0.5f*0.0938443990808045654f, 0.5f*0.0911738786957638847f,
    0.5f*0.0876520930044038111f, 0.5f*0.0833119242269467552f,
    0.5f*0.0781938957870703065f, 0.5f*0.0723457941088485062f,
    0.5f*0.0658222227763618468f, 0.5f*0.0586840934785355471f,
    0.5f*0.0509980592623761762f, 0.5f*0.0428358980222266807f,
    0.5f*0.0342738629130214331f, 0.5f*0.0253920653092620595f,
    0.5f*0.0162743947309056706f, 0.5f*0.0070186100094700966f
};

__device__ __forceinline__ float softplusf(float x) {
    return fmaxf(x, 0.0f) + log1pf(expf(-fabsf(x)));
}
__device__ __forceinline__ double softplusd(double x) {
    return fmax(x, 0.0) + log1p(exp(-fabs(x)));
}
__device__ __forceinline__ uint32_t smem_u32(const void* p) {
    uint32_t a;
    asm("{ .reg .u64 t; cvta.to.shared.u64 t, %1; cvt.u32.u64 %0, t; }" : "=r"(a) : "l"(p));
    return a;
}
__device__ __forceinline__ void mma16816(float* d, const uint32_t* a, const uint32_t* b) {
    asm volatile(
        "mma.sync.aligned.m16n8k16.row.col.f32.bf16.bf16.f32 "
        "{%0,%1,%2,%3}, {%4,%5,%6,%7}, {%8,%9}, {%0,%1,%2,%3};"
        : "+f"(d[0]), "+f"(d[1]), "+f"(d[2]), "+f"(d[3])
        : "r"(a[0]), "r"(a[1]), "r"(a[2]), "r"(a[3]), "r"(b[0]), "r"(b[1]));
}
__device__ __forceinline__ void ldsm_x4(uint32_t* r, uint32_t addr) {
    asm volatile("ldmatrix.sync.aligned.m8n8.x4.shared.b16 {%0,%1,%2,%3}, [%4];"
        : "=r"(r[0]), "=r"(r[1]), "=r"(r[2]), "=r"(r[3]) : "r"(addr));
}
__device__ __forceinline__ void ldsm_x2(uint32_t* r, uint32_t addr) {
    asm volatile("ldmatrix.sync.aligned.m8n8.x2.shared.b16 {%0,%1}, [%2];"
        : "=r"(r[0]), "=r"(r[1]) : "r"(addr));
}

// -------- split f32 -> bf16 hi/lo pair (grid-stride over float4) -------------
__global__ void cvt_bf16x2_kernel(const float* __restrict__ src,
                                  __nv_bfloat16* __restrict__ dH,
                                  __nv_bfloat16* __restrict__ dL, long n4) {
    long stride = (long)gridDim.x*blockDim.x;
    for (long i = (long)blockIdx.x*blockDim.x + threadIdx.x; i < n4; i += stride) {
        float4 v = ((const float4*)src)[i];
        __nv_bfloat16 h0 = __float2bfloat16(v.x);
        __nv_bfloat16 h1 = __float2bfloat16(v.y);
        __nv_bfloat16 h2 = __float2bfloat16(v.z);
        __nv_bfloat16 h3 = __float2bfloat16(v.w);
        __nv_bfloat16 l0 = __float2bfloat16(v.x - __bfloat162float(h0));
        __nv_bfloat16 l1 = __float2bfloat16(v.y - __bfloat162float(h1));
        __nv_bfloat16 l2 = __float2bfloat16(v.z - __bfloat162float(h2));
        __nv_bfloat16 l3 = __float2bfloat16(v.w - __bfloat162float(h3));
        ((__nv_bfloat162*)dH)[2*i+0] = __nv_bfloat162(h0, h1);
        ((__nv_bfloat162*)dH)[2*i+1] = __nv_bfloat162(h2, h3);
        ((__nv_bfloat162*)dL)[2*i+0] = __nv_bfloat162(l0, l1);
        ((__nv_bfloat162*)dL)[2*i+1] = __nv_bfloat162(l2, l3);
    }
}

// ------------- HMMA bf16x3 GEMM, double-buffered smem (R15 winner) -----------
// CTA tile 128x128, K-chunk 32, 8 warps (2m x 4n). Dynamic smem 80KB (2 bufs).
#define GMM 128
#define GNN 128
#define GKC 32
#define SRD 40
#define TILE_B (GMM*SRD*2)
#define GSMEM (TILE_B*8)

__global__ __launch_bounds__(256, 1) void gemm_bf3(
    const __nv_bfloat16* __restrict__ AH, const __nv_bfloat16* __restrict__ AL,
    const __nv_bfloat16* __restrict__ BH, const __nv_bfloat16* __restrict__ BL,
    float* __restrict__ C, int Mr, int Nr, int Kr)
{
    extern __shared__ __align__(16) char smx[];
    int tid = threadIdx.x;
    int wid = tid >> 5, lane = tid & 31;
    int wm = wid & 1, wn = wid >> 1;
    long row0 = (long)blockIdx.y * GMM;
    long col0 = (long)blockIdx.x * GNN;

    float d[4][4][4];
    #pragma unroll
    for (int i = 0; i < 4; i++)
        #pragma unroll
        for (int j = 0; j < 4; j++)
            #pragma unroll
            for (int r = 0; r < 4; r++) d[i][j][r] = 0.f;

    uint32_t sb = smem_u32(smx);

    int lrowA = lane & 15;
    int lcolA = ((lane >> 4) & 1) * 8;
    int lrowB = lane & 7;
    int lcolB = ((lane >> 3) & 1) * 8;

    int lr[4], lq[4];
    #pragma unroll
    for (int l = 0; l < 4; l++) {
        int idx = tid + l*256;
        lr[l] = idx >> 3;
        lq[l] = idx & 7;
    }

    uint2 rAh[4], rAl[4], rBh[4], rBl[4];
    #pragma unroll
    for (int l = 0; l < 4; l++) {
        long goff = (row0 + lr[l])*Kr + lq[l]*4;
        long boff = (col0 + lr[l])*Kr + lq[l]*4;
        rAh[l] = *(const uint2*)(AH + goff);
        rAl[l] = *(const uint2*)(AL + goff);
        rBh[l] = *(const uint2*)(BH + boff);
        rBl[l] = *(const uint2*)(BL + boff);
    }
    #pragma unroll
    for (int l = 0; l < 4; l++) {
        int e = (lr[l]*SRD + lq[l]*4)*2;
        *(uint2*)(smx + 0*TILE_B + e) = rAh[l];
        *(uint2*)(smx + 1*TILE_B + e) = rAl[l];
        *(uint2*)(smx + 2*TILE_B + e) = rBh[l];
        *(uint2*)(smx + 3*TILE_B + e) = rBl[l];
    }
    __syncthreads();

    int nch = Kr / GKC;
    for (int c = 0; c < nch; c++) {
        bool has_next = (c + 1 < nch);
        if (has_next) {
            int kb = (c+1)*GKC;
            #pragma unroll
            for (int l = 0; l < 4; l++) {
                long goff = (row0 + lr[l])*Kr + kb + lq[l]*4;
                long boff = (col0 + lr[l])*Kr + kb + lq[l]*4;
                rAh[l] = *(const uint2*)(AH + goff);
                rAl[l] = *(const uint2*)(AL + goff);
                rBh[l] = *(const uint2*)(BH + boff);
                rBl[l] = *(const uint2*)(BL + boff);
            }
        }

        uint32_t bufo = (uint32_t)(c & 1) * (4*TILE_B);
        uint32_t aAh = sb + bufo + 0*TILE_B;
        uint32_t aAl = sb + bufo + 1*TILE_B;
        uint32_t aBh = sb + bufo + 2*TILE_B;
        uint32_t aBl = sb + bufo + 3*TILE_B;

        #pragma unroll
        for (int ks = 0; ks < 2; ks++) {
            uint32_t ah[4][4], al[4][4], bh[4][2], bl[4][2];
            #pragma unroll
            for (int mt = 0; mt < 4; mt++) {
                int row = wm*64 + mt*16 + lrowA;
                uint32_t off = (uint32_t)(row*SRD + ks*16 + lcolA) * 2u;
                ldsm_x4(ah[mt], aAh + off);
                ldsm_x4(al[mt], aAl + off);
            }
            #pragma unroll
            for (int nt = 0; nt < 4; nt++) {
                int row = wn*32 + nt*8 + lrowB;
                uint32_t off = (uint32_t)(row*SRD + ks*16 + lcolB) * 2u;
                ldsm_x2(bh[nt], aBh + off);
                ldsm_x2(bl[nt], aBl + off);
            }
            #pragma unroll
            for (int mt = 0; mt < 4; mt++)
                #pragma unroll
                for (int nt = 0; nt < 4; nt++) {
                    mma16816(d[mt][nt], ah[mt], bh[nt]);
                    mma16816(d[mt][nt], ah[mt], bl[nt]);
                    mma16816(d[mt][nt], al[mt], bh[nt]);
                }
        }
        if (has_next) {
            char* dst = smx + ((c+1) & 1) * (4*TILE_B);
            #pragma unroll
            for (int l = 0; l < 4; l++) {
                int e = (lr[l]*SRD + lq[l]*4)*2;
                *(uint2*)(dst + 0*TILE_B + e) = rAh[l];
                *(uint2*)(dst + 1*TILE_B + e) = rAl[l];
                *(uint2*)(dst + 2*TILE_B + e) = rBh[l];
                *(uint2*)(dst + 3*TILE_B + e) = rBl[l];
            }
            __syncthreads();
        }
    }

    #pragma unroll
    for (int mt = 0; mt < 4; mt++) {
        long r0 = row0 + wm*64 + mt*16 + (lane >> 2);
        #pragma unroll
        for (int nt = 0; nt < 4; nt++) {
            long cc = col0 + wn*32 + nt*8 + (lane & 3)*2;
            *(float2*)(C + r0*Nr + cc)     = make_float2(d[mt][nt][0], d[mt][nt][1]);
            *(float2*)(C + (r0+8)*Nr + cc) = make_float2(d[mt][nt][2], d[mt][nt][3]);
        }
    }
}

// -------- merged: gather base row + logs + phi dot (one block per j) ---------
__global__ __launch_bounds__(768) void prep_kernel(const int* __restrict__ ids,
                                                   const float* __restrict__ emb,
                                                   const float* __restrict__ gw) {
    int j = blockIdx.x;
    int tid = threadIdx.x;
    __shared__ float red[24];
    int id = ids[j];
    float v = emb[(long)id*HH + tid];
    g_base[j*HH + tid] = v;
    float s = v * gw[HH + tid];
    #pragma unroll
    for (int o = 16; o; o >>= 1) s += __shfl_xor_sync(0xffffffffu, s, o);
    int w = tid >> 5, lane = tid & 31;
    if (lane == 0) red[w] = s;
    __syncthreads();
    if (tid == 0) {
        float tot = 0.f;
        for (int i = 0; i < 24; i++) tot += red[i];
        g_phi[j] = tot;
        float x = ((float)j + 0.5f) * (1.0f/(float)SS);
        x = fminf(fmaxf(x, 1e-5f), 1.0f - 1e-5f);
        g_Lx[j] = logf(x);
        g_L1[j] = log1pf(-x);
    }
}

// focus (64) + imp (32) projections, one block per t
__global__ __launch_bounds__(256) void proj96_kernel(
    const float* __restrict__ hpen,
    const float* __restrict__ fw, const float* __restrict__ fb,
    const float* __restrict__ iw, const float* __restrict__ ib)
{
    int t = blockIdx.x, tid = threadIdx.x;
    int w = tid >> 5, lane = tid & 31;
    __shared__ float row[HH];
    for (int h = tid; h < HH; h += 256) row[h] = hpen[t*HH + h];
    __syncthreads();
    #pragma unroll
    for (int i = 0; i < 12; i++) {
        int n = w*12 + i;
        const float* W = (n < 64) ? (fw + (long)n*HH) : (iw + (long)(n-64)*HH);
        float s = 0.f;
        for (int h = lane; h < HH; h += 32) s += row[h]*W[h];
        #pragma unroll
        for (int o = 16; o; o >>= 1) s += __shfl_xor_sync(0xffffffffu, s, o);
        if (lane == 0) {
            if (n < 64) g_fpraw[t*64 + n] = s + fb[n];
            else        g_impraw[t*32 + n - 64] = s + ib[n-64];
        }
    }
}

// ------------- merged params (softplus+lgamma) + warp top-k ------------------
__global__ void params_topk_kernel() {
    int t = blockIdx.x, k = threadIdx.x;
    float fa = 0.f, fb = 0.f, im = 0.f;
    if (t > 0) {
        fa = g_fpraw[(t-1)*(KK*2) + k*2 + 0];
        fb = g_fpraw[(t-1)*(KK*2) + k*2 + 1];
        im = softplusf(g_impraw[(t-1)*KK + k]);
    }
    double al = softplusd((double)fa) + 1e-4;
    double be = softplusd((double)fb) + 1e-4;
    double ln = lgamma(al) + lgamma(be) - lgamma(al + be);
    g_a1d[t*KK+k] = al - 1.0;
    g_b1d[t*KK+k] = be - 1.0;
    g_lnd[t*KK+k] = ln;
    g_a1[t*KK+k] = (float)(al - 1.0);
    g_b1[t*KK+k] = (float)(be - 1.0);
    g_lnrm[t*KK+k] = (float)ln;
    g_imp[t*KK+k] = im;
    float v = im;
    for (int m = 0; m < MM; m++) {
        float bv = v; int bi = k;
        #pragma unroll
        for (int o = 16; o; o >>= 1) {
            float ov = __shfl_xor_sync(0xffffffffu, bv, o);
            int oi = __shfl_xor_sync(0xffffffffu, bi, o);
            if (ov > bv || (ov == bv && oi < bi)) { bv = ov; bi = oi; }
        }
        if (k == 0) g_top[t*MM + m] = bi;
        if (k == bi) v = -__int_as_float(0x7f800000);
    }
}

// ---- Z/P sums, half range, longest-first: t = thi - blockIdx.x --------------
__global__ __launch_bounds__(256) void zsum_kernel(int thi) {
    int t = thi - blockIdx.x;
    int tid = threadIdx.x;
    int k = tid & 31, jg = tid >> 5;
    __shared__ float a1s[KK], b1s[KK], lns[KK];
    __shared__ float rz[256], rp[256];
    if (tid < KK) {
        a1s[tid] = g_a1[t*KK+tid];
        b1s[tid] = g_b1[t*KK+tid];
        lns[tid] = g_lnrm[t*KK+tid];
    }
    __syncthreads();
    float a = a1s[k], b = b1s[k], ln = lns[k];
    float z = 0.f, p = 0.f;
    for (int j = jg; j <= t; j += 8) {
        float e = __expf(fmaf(a, g_Lx[j], fmaf(b, g_L1[j], -ln)));
        z += e;
        p = fmaf(e, g_phi[j], p);
    }
    rz[tid] = z; rp[tid] = p;
    __syncthreads();
    if (tid < KK) {
        float sz = 0.f, sp = 0.f;
        #pragma unroll
        for (int g = 0; g < 8; g++) { sz += rz[g*32 + tid]; sp += rp[g*32 + tid]; }
        g_Z[t*KK + tid] = sz;
        g_P[t*KK + tid] = sp;
    }
}

// ---- chunk rows for top-8 k, TWO t per block; pidx = phi_idx - blockIdx.x ---
__global__ __launch_bounds__(768, 2) void chunksel_kernel(int phi_idx) {
    int pidx = phi_idx - blockIdx.x;
    int t0 = 2*pidx;
    int t1 = t0 + 1;
    int tid = threadIdx.x;
    __shared__ float a16[16], b16[16], l16[16], sca16[16];
    __shared__ float buf[2][JT*16];

    if (tid < 16) {
        int tt = t0 + (tid >> 3);
        int k = g_top[tt*MM + (tid & 7)];
        a16[tid] = g_a1[tt*KK + k];
        b16[tid] = g_b1[tt*KK + k];
        l16[tid] = g_lnrm[tt*KK + k];
        sca16[tid] = g_imp[tt*KK + k] / (g_Z[tt*KK + k] + 1e-9f);
    }
    __syncthreads();

    float acc[16];
    #pragma unroll
    for (int m = 0; m < 16; m++) acc[m] = 0.f;

    int ntiles = (t1 + JT) / JT;

    for (int v = tid; v < JT*16; v += 768) {
        int jl = v >> 4, s = v & 15;
        int tt = t0 + (s >> 3);
        float e = 0.f;
        if (jl <= tt)
            e = __expf(fmaf(a16[s], g_Lx[jl], fmaf(b16[s], g_L1[jl], -l16[s])));
        buf[0][v] = e;
    }
    __syncthreads();

    for (int tile = 0; tile < ntiles; tile++) {
        int p = tile & 1;
        if (tile + 1 < ntiles) {
            int jb = (tile+1)*JT;
            for (int v = tid; v < JT*16; v += 768) {
                int jl = v >> 4, s = v & 15;
                int j = jb + jl;
                int tt = t0 + (s >> 3);
                float e = 0.f;
                if (j <= tt)
                    e = __expf(fmaf(a16[s], g_Lx[j], fmaf(b16[s], g_L1[j], -l16[s])));
                buf[1-p][v] = e;
            }
        }
        int jb = tile*JT;
        int jend = min(jb + JT - 1, t1);
        #pragma unroll 2
        for (int j = jb; j <= jend; j++) {
            float b = g_base[j*HH + tid];
            const float4* w4 = (const float4*)&buf[p][(j - jb)*16];
            #pragma unroll
            for (int q = 0; q < 4; q++) {
                float4 w = w4[q];
                acc[4*q+0] = fmaf(w.x, b, acc[4*q+0]);
                acc[4*q+1] = fmaf(w.y, b, acc[4*q+1]);
                acc[4*q+2] = fmaf(w.z, b, acc[4*q+2]);
                acc[4*q+3] = fmaf(w.w, b, acc[4*q+3]);
            }
        }
        __syncthreads();
    }

    #pragma unroll
    for (int m = 0; m < MM; m++) {
        g_sel[((long)t0*MM + m)*HH + tid] = acc[m]     * sca16[m];
        g_sel[((long)t1*MM + m)*HH + tid] = acc[8 + m] * sca16[8 + m];
    }
}

// ------------------------ generic SGEMM: C = A @ B^T + bias ----------------
#define BM 64
#define BN 64
#define BK 16
__global__ __launch_bounds__(256) void sgemm_bias(
    const float* __restrict__ A, const float* __restrict__ B,
    const float* __restrict__ bias, float* __restrict__ C,
    int Mr, int Nr, int Kr)
{
    __shared__ float As[BK][BM+4];
    __shared__ float Bs[BK][BN+4];
    int tx = threadIdx.x & 15;
    int ty = threadIdx.x >> 4;
    int row0 = blockIdx.y*BM;
    int col0 = blockIdx.x*BN;
    float acc[4][4];
    #pragma unroll
    for (int i = 0; i < 4; i++)
        #pragma unroll
        for (int j = 0; j < 4; j++) acc[i][j] = 0.f;

    for (int k0 = 0; k0 < Kr; k0 += BK) {
        #pragma unroll
        for (int l = 0; l < 4; l++) {
            int lin = threadIdx.x + l*256;
            int r = lin >> 4, c = lin & 15;
            int gr = row0 + r;
            As[c][r] = (gr < Mr) ? A[(long)gr*Kr + k0 + c] : 0.f;
        }
        #pragma unroll
        for (int l = 0; l < 4; l++) {
            int lin = threadIdx.x + l*256;
            int r = lin >> 4, c = lin & 15;
            int gc = col0 + r;
            Bs[c][r] = (gc < Nr) ? B[(long)gc*Kr + k0 + c] : 0.f;
        }
        __syncthreads();
        #pragma unroll
        for (int c = 0; c < BK; c++) {
            float4 a4 = *(const float4*)&As[c][ty*4];
            float4 b4 = *(const float4*)&Bs[c][tx*4];
            float ar[4] = {a4.x, a4.y, a4.z, a4.w};
            float br[4] = {b4.x, b4.y, b4.z, b4.w};
            #pragma unroll
            for (int i = 0; i < 4; i++)
                #pragma unroll
                for (int j = 0; j < 4; j++)
                    acc[i][j] = fmaf(ar[i], br[j], acc[i][j]);
        }
        __syncthreads();
    }
    #pragma unroll
    for (int i = 0; i < 4; i++) {
        int gr = row0 + ty*4 + i;
        if (gr >= Mr) continue;
        #pragma unroll
        for (int j = 0; j < 4; j++) {
            int gc = col0 + tx*4 + j;
            if (gc >= Nr) continue;
            float v = acc[i][j];
            if (bias) v += bias[gc];
            C[(long)gr*Nr + gc] = v;
        }
    }
}

// ---------- SGEMM-TN: C[i,j] = sum_k A[k,i] * B[k,j] -------------------------
__global__ __launch_bounds__(256) void sgemm_tn(
    const float* __restrict__ A, const float* __restrict__ B,
    float* __restrict__ C, int Mr, int Nr, int Kr)
{
    __shared__ float As[BK][BM+4];
    __shared__ float Bs[BK][BN+4];
    int tx = threadIdx.x & 15;
    int ty = threadIdx.x >> 4;
    int row0 = blockIdx.y*BM;
    int col0 = blockIdx.x*BN;
    float acc[4][4];
    #pragma unroll
    for (int i = 0; i < 4; i++)
        #pragma unroll
        for (int j = 0; j < 4; j++) acc[i][j] = 0.f;

    for (int k0 = 0; k0 < Kr; k0 += BK) {
        #pragma unroll
        for (int l = 0; l < 4; l++) {
            int lin = threadIdx.x + l*256;
            int r = lin & 63, c = lin >> 6;
            As[c][r] = A[(long)(k0 + c)*Mr + row0 + r];
        }
        #pragma unroll
        for (int l = 0; l < 4; l++) {
            int lin = threadIdx.x + l*256;
            int r = lin & 63, c = lin >> 6;
            Bs[c][r] = B[(long)(k0 + c)*Nr + col0 + r];
        }
        __syncthreads();
        #pragma unroll
        for (int c = 0; c < BK; c++) {
            float4 a4 = *(const float4*)&As[c][ty*4];
            float4 b4 = *(const float4*)&Bs[c][tx*4];
            float ar[4] = {a4.x, a4.y, a4.z, a4.w};
            float br[4] = {b4.x, b4.y, b4.z, b4.w};
            #pragma unroll
            for (int i = 0; i < 4; i++)
                #pragma unroll
                for (int j = 0; j < 4; j++)
                    acc[i][j] = fmaf(ar[i], br[j], acc[i][j]);
        }
        __syncthreads();
    }
    #pragma unroll
    for (int i = 0; i < 4; i++) {
        int gr = row0 + ty*4 + i;
        #pragma unroll
        for (int j = 0; j < 4; j++)
            C[(long)gr*Nr + col0 + tx*4 + j] = acc[i][j];
    }
}

// ---- ub[h'] = qb.kw[:,h'];  kbv[hf] = qw[:,hf].kb;  kbc = qb.kb -------------
__global__ void prebias_kernel(const float* __restrict__ qw, const float* __restrict__ qb,
                               const float* __restrict__ kw, const float* __restrict__ kb) {
    int i = blockIdx.x*256 + threadIdx.x;
    if (i < HH) {
        float s = 0.f;
        for (int h = 0; h < HH; h++) s = fmaf(qb[h], kw[(long)h*HH + i], s);
        g_ub[i] = s;
    } else if (i < 2*HH) {
        int j = i - HH;
        float s = 0.f;
        for (int h = 0; h < HH; h++) s = fmaf(qw[(long)h*HH + j], kb[h], s);
        g_kbv[j] = s;
    } else if (i == 2*HH) {
        float s = 0.f;
        for (int h = 0; h < HH; h++) s = fmaf(qb[h], kb[h], s);
        g_kbc_v = s;
    }
}

// ------------------------------- attention (t offset) ------------------------
__global__ __launch_bounds__(288) void attn2_kernel(const float* __restrict__ hfin, int tbase) {
    int t = tbase + blockIdx.x, tid = threadIdx.x;
    int w = tid >> 5, lane = tid & 31;
    __shared__ float sc[9], at[MM];
    float s = 0.f;
    if (w < MM) {
        const float* sel = g_sel + ((long)t*MM + w)*HH;
        for (int h = lane; h < HH; h += 32) s += g_u[t*HH + h]*sel[h];
    } else {
        for (int h = lane; h < HH; h += 32) s += hfin[t*HH + h]*g_kbv[h];
    }
    #pragma unroll
    for (int o = 16; o; o >>= 1) s += __shfl_xor_sync(0xffffffffu, s, o);
    if (lane == 0) sc[w] = s;
    __syncthreads();
    if (tid == 0) {
        float extra = sc[8] + g_kbc_v;
        const float isq = 1.0f/27.712812921102035f;
        float v[MM], mx = -3.4e38f;
        for (int m = 0; m < MM; m++) { v[m] = (sc[m] + extra)*isq; mx = fmaxf(mx, v[m]); }
        float ssum = 0.f;
        for (int m = 0; m < MM; m++) { float e = expf(v[m]-mx); at[m] = e; ssum += e; }
        float inv = 1.0f/ssum;
        for (int m = 0; m < MM; m++) at[m] *= inv;
    }
    __syncthreads();
    for (int h = tid; h < HH; h += 288) {
        float f = 0.f;
        #pragma unroll
        for (int m = 0; m < MM; m++)
            f = fmaf(at[m], g_sel[((long)t*MM + m)*HH + h], f);
        g_ctx[t*HH + h] = f;
    }
}

// ---------------- merged gate + gated residual + LN (t offset) ---------------
__global__ __launch_bounds__(256) void lngate_kernel(const float* __restrict__ hpen,
                                                     const float* __restrict__ gw,
                                                     const float* __restrict__ gb,
                                                     const float* __restrict__ hfin,
                                                     const float* __restrict__ lng,
                                                     const float* __restrict__ lnb,
                                                     int tbase) {
    int t = tbase + blockIdx.x, tid = threadIdx.x;
    __shared__ float hb[HH];
    __shared__ float red[8];
    __shared__ float s_gate, s_mean, s_var;
    int w = tid >> 5, lane = tid & 31;

    float s = 0.f;
    for (int h = tid; h < HH; h += 256)
        s += hpen[t*HH+h]*gw[h];
    #pragma unroll
    for (int o = 16; o; o >>= 1) s += __shfl_xor_sync(0xffffffffu, s, o);
    if (lane == 0) red[w] = s;
    __syncthreads();
    if (tid == 0) {
        float tot = 0.f;
        for (int i = 0; i < 8; i++) tot += red[i];
        float s2 = 0.f;
        for (int k = 0; k < KK; k++)
            s2 = fmaf(g_imp[t*KK+k]/(g_Z[t*KK+k]+1e-9f), g_P[t*KK+k], s2);
        s2 *= (1.0f/(float)KK);
        s_gate = 1.0f/(1.0f + expf(-(tot + s2 + gb[0])));
    }
    __syncthreads();

    float gt = s_gate;
    s = 0.f;
    for (int h = tid; h < HH; h += 256) {
        float hv = gt*g_ft[t*HH+h] + (1.0f-gt)*hfin[t*HH+h];
        hb[h] = hv;
        s += hv;
    }
    #pragma unroll
    for (int o = 16; o; o >>= 1) s += __shfl_xor_sync(0xffffffffu, s, o);
    if (lane == 0) red[w] = s;
    __syncthreads();
    if (tid == 0) {
        float tot = 0.f;
        for (int i = 0; i < 8; i++) tot += red[i];
        s_mean = tot * (1.0f/(float)HH);
    }
    __syncthreads();
    float mean = s_mean;
    float v = 0.f;
    for (int h = tid; h < HH; h += 256) {
        float dd = hb[h] - mean;
        v += dd*dd;
    }
    #pragma unroll
    for (int o = 16; o; o >>= 1) v += __shfl_xor_sync(0xffffffffu, v, o);
    if (lane == 0) red[w] = v;
    __syncthreads();
    if (tid == 0) {
        float tot = 0.f;
        for (int i = 0; i < 8; i++) tot += red[i];
        s_var = tot * (1.0f/(float)HH);
    }
    __syncthreads();
    float inv = rsqrtf(s_var + 1e-5f);
    for (int h = tid; h < HH; h += 256) {
        float hv = (hb[h]-mean)*inv*lng[h] + lnb[h];
        __nv_bfloat16 hh = __float2bfloat16(hv);
        g_hidH[t*HH+h] = hh;
        g_hidL[t*HH+h] = __float2bfloat16(hv - __bfloat162float(hh));
    }
}

// ------------------------------- JS divergence -------------------------------
__global__ __launch_bounds__(512) void js_kernel() {
    int t = blockIdx.x;
    int tid = threadIdx.x;
    __shared__ double pd[KK*GG];
    __shared__ double a1s[KK], b1s[KK], lns[KK];
    __shared__ double lgx[GG], lg1[GG];
    __shared__ float gws[GG];
    __shared__ float red[16];

    if (tid < KK) {
        a1s[tid] = g_a1d[t*KK+tid];
        b1s[tid] = g_b1d[t*KK+tid];
        lns[tid] = g_lnd[t*KK+tid];
        double nd = (double)c_node[tid];
        nd = fmin(fmax(nd, 1e-5), 1.0 - 1e-5);
        lgx[tid] = log(nd);
        lg1[tid] = log1p(-nd);
        gws[tid] = c_gw[tid];
    }
    __syncthreads();
    for (int v = tid; v < KK*GG; v += 512) {
        int k = v >> 5, g = v & 31;
        pd[v] = exp(a1s[k]*lgx[g] + b1s[k]*lg1[g] - lns[k]);
    }
    __syncthreads();

    float sum = 0.f;
    if (tid < 496) {
        int idx = tid, i = 0, rem = 31;
        while (idx >= rem) { idx -= rem; i++; rem--; }
        int j = i + 1 + idx;
        #pragma unroll
        for (int g = 0; g < GG; g++) {
            double pi = pd[i*GG+g], pj = pd[j*GG+g];
            double me = 0.5*(pi+pj) + 1e-9;
            double dd = 0.5*(pi-pj);
            float inv = 1.0f/(float)me;
            float rr = (float)dd * inv;
            float term = (float)pi * log1pf(rr) + (float)pj * log1pf(-rr);
            sum += gws[g]*0.5f*term;
        }
    }
    #pragma unroll
    for (int o = 16; o; o >>= 1) sum += __shfl_xor_sync(0xffffffffu, sum, o);
    int w = tid >> 5, lane = tid & 31;
    if (lane == 0) red[w] = sum;
    __syncthreads();
    if (tid == 0) {
        float s = 0.f;
        for (int i = 0; i < 16; i++) s += red[i];
        g_jsp[t] = s;
    }
}

__global__ void jsred_kernel(float* out, int out_size) {
    __shared__ double smr[SS];
    int tid = threadIdx.x;
    smr[tid] = (double)g_jsp[tid];
    __syncthreads();
    for (int s = SS/2; s; s >>= 1) {
        if (tid < s) smr[tid] += smr[tid+s];
        __syncthreads();
    }
    if (tid == 0) out[out_size-1] = (float)(smr[0] / 507904.0);
}

// ------------------------------------------------------------------------------
extern "C" void kernel_launch(void* const* d_in, const int* in_sizes, int n_in,
                              void* d_out, int out_size) {
    const int*   ids     = (const int*)  d_in[0];
    const float* emb     = (const float*)d_in[1];
    const float* h_pen   = (const float*)d_in[2];
    const float* h_final = (const float*)d_in[3];
    const float* focus_w = (const float*)d_in[4];
    const float* focus_b = (const float*)d_in[5];
    const float* imp_w   = (const float*)d_in[6];
    const float* imp_b   = (const float*)d_in[7];
    const float* q_w     = (const float*)d_in[8];
    const float* q_b     = (const float*)d_in[9];
    const float* k_w     = (const float*)d_in[10];
    const float* k_b     = (const float*)d_in[11];
    const float* v_w     = (const float*)d_in[12];
    const float* v_b     = (const float*)d_in[13];
    const float* gate_w  = (const float*)d_in[14];
    const float* gate_b  = (const float*)d_in[15];
    const float* ln_g    = (const float*)d_in[16];
    const float* ln_b    = (const float*)d_in[17];
    const float* lm_w    = (const float*)d_in[18];
    float* out = (float*)d_out;

    float* p_W2;  cudaGetSymbolAddress((void**)&p_W2,  g_W2);
    float* p_ub;  cudaGetSymbolAddress((void**)&p_ub,  g_ub);
    float* p_u;   cudaGetSymbolAddress((void**)&p_u,   g_u);
    float* p_ctx; cudaGetSymbolAddress((void**)&p_ctx, g_ctx);
    float* p_ft;  cudaGetSymbolAddress((void**)&p_ft,  g_ft);
    __nv_bfloat16 *p_lmH, *p_lmL, *p_hidH, *p_hidL;
    cudaGetSymbolAddress((void**)&p_lmH,  g_lmH);
    cudaGetSymbolAddress((void**)&p_lmL,  g_lmL);
    cudaGetSymbolAddress((void**)&p_hidH, g_hidH);
    cudaGetSymbolAddress((void**)&p_hidL, g_hidL);

    static cudaStream_t s1 = nullptr, s2 = nullptr, s3 = nullptr;
    static cudaEvent_t evA = nullptr, evB = nullptr, evP = nullptr;
    static cudaEvent_t ev1 = nullptr, ev2 = nullptr, ev3 = nullptr, evL = nullptr;
    if (!s1) {
        cudaStreamCreateWithFlags(&s1, cudaStreamNonBlocking);
        cudaStreamCreateWithFlags(&s2, cudaStreamNonBlocking);
        cudaStreamCreateWithFlags(&s3, cudaStreamNonBlocking);
        cudaEventCreateWithFlags(&evA, cudaEventDisableTiming);
        cudaEventCreateWithFlags(&evB, cudaEventDisableTiming);
        cudaEventCreateWithFlags(&evP, cudaEventDisableTiming);
        cudaEventCreateWithFlags(&ev1, cudaEventDisableTiming);
        cudaEventCreateWithFlags(&ev2, cudaEventDisableTiming);
        cudaEventCreateWithFlags(&ev3, cudaEventDisableTiming);
        cudaEventCreateWithFlags(&evL, cudaEventDisableTiming);
        cudaFuncSetAttribute(gemm_bf3, cudaFuncAttributeMaxDynamicSharedMemorySize, GSMEM);
    }

    // ---- fork branch A: attention pre-work + lm_w bf16 split ----
    cudaEventRecord(evA, 0);
    cudaStreamWaitEvent(s1, evA, 0);
    sgemm_tn<<<dim3(HH/BN, HH/BM), 256, 0, s1>>>(k_w, q_w, p_W2, HH, HH, HH);
    prebias_kernel<<<7, 256, 0, s1>>>(q_w, q_b, k_w, k_b);
    sgemm_bias<<<dim3(HH/BN, SS/BM), 256, 0, s1>>>(h_final, p_W2, p_ub, p_u, SS, HH, HH);
    cudaEventRecord(ev1, s1);
    cvt_bf16x2_kernel<<<4096, 256, 0, s1>>>(lm_w, p_lmH, p_lmL, (long)VN*HH/4);
    cudaEventRecord(evL, s1);

    // ---- main chain (shared prefix) ----
    prep_kernel<<<SS, HH>>>(ids, emb, gate_w);
    proj96_kernel<<<SS, 256>>>(h_pen, focus_w, focus_b, imp_w, imp_b);
    params_topk_kernel<<<SS, KK>>>();
    cudaEventRecord(evP, 0);

    // ---- fork branch B: JS loss ----
    cudaStreamWaitEvent(s2, evP, 0);
    js_kernel<<<SS, 512, 0, s2>>>();
    jsred_kernel<<<1, SS, 0, s2>>>(out, out_size);
    cudaEventRecord(ev2, s2);

    // ---- fork half-1 chain on s3 (t in [512,1024)) ----
    cudaStreamWaitEvent(s3, evP, 0);
    cudaStreamWaitEvent(s3, ev1, 0);
    zsum_kernel<<<HS, 256, 0, s3>>>(SS - 1);
    chunksel_kernel<<<HS/2, HH, 0, s3>>>(SS/2 - 1);
    attn2_kernel<<<HS, 288, 0, s3>>>(h_final, HS);
    sgemm_bias<<<dim3(HH/BN, HS/BM), 256, 0, s3>>>(p_ctx + (long)HS*HH, v_w, v_b,
                                                   p_ft + (long)HS*HH, HS, HH, HH);
    lngate_kernel<<<HS, 256, 0, s3>>>(h_pen, gate_w, gate_b, h_final, ln_g, ln_b, HS);
    cudaEventRecord(ev3, s3);

    // ---- half-0 chain on main (t in [0,512)) ----
    zsum_kernel<<<HS, 256>>>(HS - 1);
    chunksel_kernel<<<HS/2, HH>>>(HS/2 - 1);
    cudaStreamWaitEvent(0, ev1, 0);
    attn2_kernel<<<HS, 288>>>(h_final, 0);
    sgemm_bias<<<dim3(HH/BN, HS/BM), 256>>>(p_ctx, v_w, v_b, p_ft, HS, HH, HH);
    lngate_kernel<<<HS, 256>>>(h_pen, gate_w, gate_b, h_final, ln_g, ln_b, 0);

    // ---- LM head, half 0 ----
    cudaStreamWaitEvent(0, evL, 0);
    gemm_bf3<<<dim3(VN/GNN, HS/GMM), 256, GSMEM>>>(p_hidH, p_hidL, p_lmH, p_lmL,
                                                   out, HS, VN, HH);

    // ---- LM head, half 1 (after its chain) ----
    cudaStreamWaitEvent(0, ev3, 0);
    gemm_bf3<<<dim3(VN/GNN, HS/GMM), 256, GSMEM>>>(p_hidH + (long)HS*HH, p_hidL + (long)HS*HH,
                                                   p_lmH, p_lmL,
                                                   out + (long)HS*VN, HS, VN, HH);

    // ---- join branch B ----
    cudaStreamWaitEvent(0, ev2, 0);
}